// round 6
// baseline (speedup 1.0000x reference)
#include <cuda_runtime.h>
#include <cstdint>

#define TOK   16384
#define DIM   2048
#define NE    16
#define BT    128
#define NTHR  512
#define NCHUNK 32                 // 32 chunks of 64 dims
#define SMEM_BYTES 131072         // W resident: 16 experts x 2048 f32

__device__ __forceinline__ uint32_t smem_u32(const void* p) {
    uint32_t a;
    asm("{ .reg .u64 t; cvta.to.shared.u64 t, %1; cvt.u32.u64 %0, t; }" : "=r"(a) : "l"(p));
    return a;
}

#define CP_ASYNC16(saddr, gptr) \
    asm volatile("cp.async.cg.shared.global [%0], [%1], 16;" :: "r"(saddr), "l"(gptr))
#define CP_COMMIT() asm volatile("cp.async.commit_group;" ::: "memory")
#define CP_WAIT0()  asm volatile("cp.async.wait_group 0;" ::: "memory")

#define FMA2(c, a, b) asm("fma.rn.f32x2 %0, %1, %2, %0;" : "+l"(c) : "l"(a), "l"(b))
#define LDSV2(a, b, addr) \
    asm volatile("ld.shared.v2.b64 {%0, %1}, [%2];" : "=l"(a), "=l"(b) : "r"(addr))

__global__ void __launch_bounds__(NTHR, 1)
gating_moe_kernel(const float* __restrict__ x,
                  const float* __restrict__ noise,
                  const float* __restrict__ W,
                  const float* __restrict__ b,
                  float* __restrict__ out)
{
    extern __shared__ float sm[];
    const uint32_t sb = smem_u32(sm);
    const int tid  = threadIdx.x;
    const int dp   = tid & 7;          // d-partition (8 dims/chunk each), lane bits 0..2
    const int pr   = tid >> 3;         // token pair 0..63
    const int tok0 = blockIdx.x * BT;

    // ---- one-time W load into dp-interleaved smem layout ----
    // global 16B chunk g -> (e = g>>9, d4 = g&511); d4 = c*16 + dp*2 + half
    // smem offset = e*8192 + c*256 + half*128 + dp*16   (W LDS = 1-wf broadcast)
    #pragma unroll
    for (int k = 0; k < 16; k++) {
        int g  = tid + NTHR * k;
        int e  = g >> 9;
        int d4 = g & 511;
        int c  = d4 >> 4;
        int r  = d4 & 15;
        int wdp  = r >> 1;
        int half = r & 1;
        uint32_t soff = (uint32_t)(e * 8192 + c * 256 + half * 128 + wdp * 16);
        CP_ASYNC16(sb + soff, (const char*)W + (size_t)g * 16);
    }
    CP_COMMIT(); CP_WAIT0();
    __syncthreads();

    // ---- mainloop: 2 tokens x 16 experts x 8 dims/chunk, x via LDG double-buffer ----
    const float* xp0 = x + (size_t)(tok0 + 2 * pr) * DIM + dp * 8;
    const float* xp1 = xp0 + DIM;

    unsigned long long acc[2][16];
    #pragma unroll
    for (int t = 0; t < 2; t++)
        #pragma unroll
        for (int e = 0; e < 16; e++) acc[t][e] = 0ULL;

    ulonglong2 a0 = *(const ulonglong2*)(xp0);
    ulonglong2 a1 = *(const ulonglong2*)(xp0 + 4);
    ulonglong2 b0 = *(const ulonglong2*)(xp1);
    ulonglong2 b1 = *(const ulonglong2*)(xp1 + 4);

    const uint32_t wb = sb + (uint32_t)(dp * 16);

    for (int c = 0; c < NCHUNK; c++) {
        ulonglong2 ca0 = a0, ca1 = a1, cb0 = b0, cb1 = b1;
        if (c + 1 < NCHUNK) {
            a0 = *(const ulonglong2*)(xp0 + (c + 1) * 64);
            a1 = *(const ulonglong2*)(xp0 + (c + 1) * 64 + 4);
            b0 = *(const ulonglong2*)(xp1 + (c + 1) * 64);
            b1 = *(const ulonglong2*)(xp1 + (c + 1) * 64 + 4);
        }
        const uint32_t cwb = wb + (uint32_t)(c * 256);
        #pragma unroll
        for (int e = 0; e < 16; e++) {
            unsigned long long w0, w1, w2, w3;
            LDSV2(w0, w1, cwb + (uint32_t)(e * 8192));        // pairs 0,1
            LDSV2(w2, w3, cwb + (uint32_t)(e * 8192) + 128u); // pairs 2,3
            FMA2(acc[0][e], ca0.x, w0);
            FMA2(acc[0][e], ca0.y, w1);
            FMA2(acc[0][e], ca1.x, w2);
            FMA2(acc[0][e], ca1.y, w3);
            FMA2(acc[1][e], cb0.x, w0);
            FMA2(acc[1][e], cb0.y, w1);
            FMA2(acc[1][e], cb1.x, w2);
            FMA2(acc[1][e], cb1.y, w3);
        }
    }

    // ---- reduce: halves add + butterfly over dp (lane bits 0..2) ----
    float lg[2][16];
    #pragma unroll
    for (int t = 0; t < 2; t++) {
        #pragma unroll
        for (int e = 0; e < 16; e++) {
            float lo = __uint_as_float((unsigned)(acc[t][e] & 0xffffffffULL));
            float hi = __uint_as_float((unsigned)(acc[t][e] >> 32));
            float s = lo + hi;
            s += __shfl_xor_sync(~0u, s, 1);
            s += __shfl_xor_sync(~0u, s, 2);
            s += __shfl_xor_sync(~0u, s, 4);
            lg[t][e] = s;
        }
    }

    // ---- epilogue (dp==0 lanes): bias + noise + top-2 + softmax + dense out ----
    if (dp == 0) {
        const float4* bb4 = (const float4*)b;
        float4 q0 = bb4[0], q1 = bb4[1], q2 = bb4[2], q3 = bb4[3];
        float bv[16] = {q0.x, q0.y, q0.z, q0.w, q1.x, q1.y, q1.z, q1.w,
                        q2.x, q2.y, q2.z, q2.w, q3.x, q3.y, q3.z, q3.w};
        #pragma unroll
        for (int t = 0; t < 2; t++) {
            const int gtok = tok0 + 2 * pr + t;
            const float4* nz = (const float4*)(noise + (size_t)gtok * NE);
            float4 n0 = nz[0], n1 = nz[1], n2 = nz[2], n3 = nz[3];
            float nn[16] = {n0.x, n0.y, n0.z, n0.w, n1.x, n1.y, n1.z, n1.w,
                            n2.x, n2.y, n2.z, n2.w, n3.x, n3.y, n3.z, n3.w};

            float v[16];
            #pragma unroll
            for (int e = 0; e < 16; e++)
                v[e] = lg[t][e] + bv[e] + 0.1f * nn[e];

            float v1 = -1e30f, v2 = -1e30f;
            int   i1 = -1,     i2 = -1;
            #pragma unroll
            for (int e = 0; e < 16; e++) {
                float val = v[e];
                if (val > v1)      { v2 = v1; i2 = i1; v1 = val; i1 = e; }
                else if (val > v2) { v2 = val; i2 = e; }
            }

            float ew  = expf(v2 - v1);
            float inv = 1.0f / (1.0f + ew);
            float w1  = inv;
            float w2  = ew * inv;

            float o[16];
            #pragma unroll
            for (int e = 0; e < 16; e++)
                o[e] = (e == i1) ? w1 : ((e == i2) ? w2 : 0.0f);

            float4* op = (float4*)(out + (size_t)gtok * NE);
            op[0] = make_float4(o[0],  o[1],  o[2],  o[3]);
            op[1] = make_float4(o[4],  o[5],  o[6],  o[7]);
            op[2] = make_float4(o[8],  o[9],  o[10], o[11]);
            op[3] = make_float4(o[12], o[13], o[14], o[15]);
        }
    }
}

extern "C" void kernel_launch(void* const* d_in, const int* in_sizes, int n_in,
                              void* d_out, int out_size)
{
    const float* x     = (const float*)d_in[0];
    const float* noise = (const float*)d_in[1];
    const float* W     = (const float*)d_in[2];
    const float* b     = (const float*)d_in[3];
    float* out = (float*)d_out;

    cudaFuncSetAttribute(gating_moe_kernel,
                         cudaFuncAttributeMaxDynamicSharedMemorySize, SMEM_BYTES);
    gating_moe_kernel<<<TOK / BT, NTHR, SMEM_BYTES>>>(x, noise, W, b, out);
}

// round 8
// speedup vs baseline: 1.0267x; 1.0267x over previous
#include <cuda_runtime.h>
#include <cstdint>

#define TOK    16384
#define DIM    2048
#define NE     16
#define BT     128
#define NTHR   256
#define NCHUNK 32            // K chunks of 64
#define NSTAGE 4

// stage: x[step0..7][tok0..127][8f] = 32768 B ; W[step][e0..15][8f] = 4096 B
#define XSTAGE_B 32768u
#define STAGE_B  36864u
#define SMEM_BYTES (4 * 36864)   // 147456; logits reuse stage 0

__device__ __forceinline__ uint32_t smem_u32(const void* p) {
    uint32_t a;
    asm("{ .reg .u64 t; cvta.to.shared.u64 t, %1; cvt.u32.u64 %0, t; }" : "=r"(a) : "l"(p));
    return a;
}

#define CP_ASYNC16(saddr, gptr) \
    asm volatile("cp.async.cg.shared.global [%0], [%1], 16;" :: "r"(saddr), "l"(gptr))
#define CP_COMMIT() asm volatile("cp.async.commit_group;" ::: "memory")
#define CP_WAIT2()  asm volatile("cp.async.wait_group 2;" ::: "memory")
#define CP_WAIT1()  asm volatile("cp.async.wait_group 1;" ::: "memory")
#define CP_WAIT0()  asm volatile("cp.async.wait_group 0;" ::: "memory")

#define LDS64(a, b, addr) \
    asm volatile("ld.shared.v2.f32 {%0, %1}, [%2];" : "=f"(a), "=f"(b) : "r"(addr))
#define STS64(addr, a, b) \
    asm volatile("st.shared.v2.f32 [%0], {%1, %2};" :: "r"(addr), "f"(a), "f"(b))
#define LDS32(v, addr) asm volatile("ld.shared.f32 %0, [%1];" : "=f"(v) : "r"(addr))
#define CVT_TF32(h, v) asm("cvt.rna.tf32.f32 %0, %1;" : "=r"(h) : "f"(v))

#define MMA_TF32(d, a0, a1, a2, a3, b0, b1)                               \
    asm volatile("mma.sync.aligned.m16n8k8.row.col.f32.tf32.tf32.f32 "    \
        "{%0,%1,%2,%3}, {%4,%5,%6,%7}, {%8,%9}, {%0,%1,%2,%3};"           \
        : "+f"(d[0]), "+f"(d[1]), "+f"(d[2]), "+f"(d[3])                  \
        : "r"(a0), "r"(a1), "r"(a2), "r"(a3), "r"(b0), "r"(b1))

__global__ void __launch_bounds__(NTHR, 1)
gating_moe_kernel(const float* __restrict__ x,
                  const float* __restrict__ noise,
                  const float* __restrict__ W,
                  const float* __restrict__ b,
                  float* __restrict__ out)
{
    extern __shared__ float sm[];
    const uint32_t sb = smem_u32(sm);
    const int tid  = threadIdx.x;
    const int wid  = tid >> 5;         // 8 warps, warp owns tokens [wid*16, wid*16+16)
    const int l    = tid & 31;
    const int grp  = l >> 2;           // fragment group id
    const int pr   = l & 3;            // k-pair id (phys cols 2pr, 2pr+1 via perm)
    const int tok0 = blockIdx.x * BT;

    // ---- cp.async fill: chunk c -> stage s ----
    auto prefetch = [&](int c, int s) {
        const uint32_t base = sb + (uint32_t)s * STAGE_B;
        #pragma unroll
        for (int k = 0; k < 8; k++) {
            int idx = tid + NTHR * k;
            int t  = idx >> 4;
            int dv = idx & 15;
            const float* g = x + (size_t)(tok0 + t) * DIM + c * 64 + dv * 4;
            CP_ASYNC16(base + (uint32_t)((dv >> 1) * 4096 + t * 32 + (dv & 1) * 16), g);
        }
        {
            int e  = tid >> 4;
            int dv = tid & 15;
            const float* g = W + (size_t)e * DIM + c * 64 + dv * 4;
            CP_ASYNC16(base + XSTAGE_B + (uint32_t)((dv >> 1) * 512 + e * 32 + (dv & 1) * 16), g);
        }
    };

    float d0[4] = {0.f, 0.f, 0.f, 0.f};   // experts 0-7 tile
    float d1[4] = {0.f, 0.f, 0.f, 0.f};   // experts 8-15 tile

    prefetch(0, 0); CP_COMMIT();
    prefetch(1, 1); CP_COMMIT();
    prefetch(2, 2); CP_COMMIT();

    // per-thread LDS bases (within a stage)
    const uint32_t aoff = (uint32_t)((wid * 16 + grp) * 32 + pr * 8);   // row grp
    const uint32_t boff = (uint32_t)(grp * 32 + pr * 8);                // expert grp

    for (int c = 0; c < NCHUNK; c++) {
        if (c < NCHUNK - 2)       { CP_WAIT2(); }
        else if (c == NCHUNK - 2) { CP_WAIT1(); }
        else                      { CP_WAIT0(); }
        __syncthreads();
        if (c + 3 < NCHUNK) { prefetch(c + 3, (c + 3) & 3); CP_COMMIT(); }

        const uint32_t xs = sb + (uint32_t)(c & 3) * STAGE_B;
        const uint32_t ws = xs + XSTAGE_B;

        #pragma unroll
        for (int st = 0; st < 8; st++) {
            float aL0, aL1, aH0, aH1;                  // rows grp / grp+8
            LDS64(aL0, aL1, xs + (uint32_t)(st * 4096) + aoff);
            LDS64(aH0, aH1, xs + (uint32_t)(st * 4096) + aoff + 256u);
            float b00, b01, b10, b11;                  // tiles 0 / 1
            LDS64(b00, b01, ws + (uint32_t)(st * 512) + boff);
            LDS64(b10, b11, ws + (uint32_t)(st * 512) + boff + 256u);

            // hi = tf32(v); lo = v - hi (fed raw, HW truncates)
            uint32_t ah0, ah1, ah2, ah3, bh00, bh01, bh10, bh11;
            CVT_TF32(ah0, aL0); CVT_TF32(ah1, aH0);
            CVT_TF32(ah2, aL1); CVT_TF32(ah3, aH1);
            CVT_TF32(bh00, b00); CVT_TF32(bh01, b01);
            CVT_TF32(bh10, b10); CVT_TF32(bh11, b11);
            uint32_t al0 = __float_as_uint(aL0 - __uint_as_float(ah0));
            uint32_t al1 = __float_as_uint(aH0 - __uint_as_float(ah1));
            uint32_t al2 = __float_as_uint(aL1 - __uint_as_float(ah2));
            uint32_t al3 = __float_as_uint(aH1 - __uint_as_float(ah3));
            uint32_t bl00 = __float_as_uint(b00 - __uint_as_float(bh00));
            uint32_t bl01 = __float_as_uint(b01 - __uint_as_float(bh01));
            uint32_t bl10 = __float_as_uint(b10 - __uint_as_float(bh10));
            uint32_t bl11 = __float_as_uint(b11 - __uint_as_float(bh11));

            MMA_TF32(d0, ah0, ah1, ah2, ah3, bh00, bh01);
            MMA_TF32(d1, ah0, ah1, ah2, ah3, bh10, bh11);
            MMA_TF32(d0, ah0, ah1, ah2, ah3, bl00, bl01);
            MMA_TF32(d1, ah0, ah1, ah2, ah3, bl10, bl11);
            MMA_TF32(d0, al0, al1, al2, al3, bh00, bh01);
            MMA_TF32(d1, al0, al1, al2, al3, bh10, bh11);
        }
    }
    __syncthreads();    // pipeline done; reuse smem base for logits [128][18]

    // ---- scatter accumulators to logits buffer ----
    {
        const int rA = wid * 16 + grp;
        const int rB = rA + 8;
        const int cb = 2 * pr;
        STS64(sb + (uint32_t)(rA * 18 + cb) * 4u,      d0[0], d0[1]);
        STS64(sb + (uint32_t)(rB * 18 + cb) * 4u,      d0[2], d0[3]);
        STS64(sb + (uint32_t)(rA * 18 + 8 + cb) * 4u,  d1[0], d1[1]);
        STS64(sb + (uint32_t)(rB * 18 + 8 + cb) * 4u,  d1[2], d1[3]);
    }
    __syncthreads();

    // ---- epilogue: one token per thread (threads 0..127) ----
    if (tid < BT) {
        const int gtok = tok0 + tid;
        const float4* nz = (const float4*)(noise + (size_t)gtok * NE);
        float4 n0 = nz[0], n1 = nz[1], n2 = nz[2], n3 = nz[3];
        const float4* bb4 = (const float4*)b;
        float4 q0 = bb4[0], q1 = bb4[1], q2 = bb4[2], q3 = bb4[3];

        float nn[16] = {n0.x, n0.y, n0.z, n0.w, n1.x, n1.y, n1.z, n1.w,
                        n2.x, n2.y, n2.z, n2.w, n3.x, n3.y, n3.z, n3.w};
        float bv[16] = {q0.x, q0.y, q0.z, q0.w, q1.x, q1.y, q1.z, q1.w,
                        q2.x, q2.y, q2.z, q2.w, q3.x, q3.y, q3.z, q3.w};

        float v[16];
        #pragma unroll
        for (int e = 0; e < 16; e++) {
            float lg;
            LDS32(lg, sb + (uint32_t)(tid * 18 + e) * 4u);
            v[e] = lg + bv[e] + 0.1f * nn[e];
        }

        // top-2 (stable: earlier index wins ties, matching jax top_k)
        float v1 = -1e30f, v2 = -1e30f;
        int   i1 = -1,     i2 = -1;
        #pragma unroll
        for (int e = 0; e < 16; e++) {
            float val = v[e];
            if (val > v1)      { v2 = v1; i2 = i1; v1 = val; i1 = e; }
            else if (val > v2) { v2 = val; i2 = e; }
        }

        float ew  = expf(v2 - v1);
        float inv = 1.0f / (1.0f + ew);
        float w1  = inv;
        float w2  = ew * inv;

        float o[16];
        #pragma unroll
        for (int e = 0; e < 16; e++)
            o[e] = (e == i1) ? w1 : ((e == i2) ? w2 : 0.0f);

        float4* op = (float4*)(out + (size_t)gtok * NE);
        op[0] = make_float4(o[0],  o[1],  o[2],  o[3]);
        op[1] = make_float4(o[4],  o[5],  o[6],  o[7]);
        op[2] = make_float4(o[8],  o[9],  o[10], o[11]);
        op[3] = make_float4(o[12], o[13], o[14], o[15]);
    }
}

extern "C" void kernel_launch(void* const* d_in, const int* in_sizes, int n_in,
                              void* d_out, int out_size)
{
    const float* x     = (const float*)d_in[0];
    const float* noise = (const float*)d_in[1];
    const float* W     = (const float*)d_in[2];
    const float* b     = (const float*)d_in[3];
    float* out = (float*)d_out;

    cudaFuncSetAttribute(gating_moe_kernel,
                         cudaFuncAttributeMaxDynamicSharedMemorySize, SMEM_BYTES);
    gating_moe_kernel<<<TOK / BT, NTHR, SMEM_BYTES>>>(x, noise, W, b, out);
}